// round 1
// baseline (speedup 1.0000x reference)
#include <cuda_runtime.h>

#define Nn   200000
#define Ee   3200000
#define Bb   512
#define EMB  32
#define HID  64

// ---------------- scratch (device globals; no allocation allowed) ----------------
__device__ float4 g_h0  [Nn * EMB / 4];   // 25.6 MB  node features layer0
__device__ float4 g_agg1[Nn * EMB / 4];   // 25.6 MB  neighbor sums layer1
__device__ float4 g_h1  [Nn * HID / 4];   // 51.2 MB  node features layer1
__device__ float4 g_agg2[Nn * HID / 4];   // 51.2 MB  neighbor sums layer2
__device__ float  g_hg  [Bb * HID];       // per-graph sums
__device__ float  g_cnt [Bb];             // per-graph node counts
__device__ int    g_deg [Nn];             // in-degree
__device__ float  g_dinv[Nn];             // 1/deg (0 if isolated)

// vectorized no-return global reduction (sm_90+)
__device__ __forceinline__ void red4(float4* p, float4 v) {
    asm volatile("red.global.add.v4.f32 [%0], {%1,%2,%3,%4};"
                 :: "l"(p), "f"(v.x), "f"(v.y), "f"(v.z), "f"(v.w) : "memory");
}

// ---------------- kernels ----------------

__global__ void k_zero() {
    int i = blockIdx.x * blockDim.x + threadIdx.x;
    int stride = gridDim.x * blockDim.x;
    const float4 z = make_float4(0.f, 0.f, 0.f, 0.f);
    for (int j = i; j < Nn * EMB / 4; j += stride) g_agg1[j] = z;
    for (int j = i; j < Nn * HID / 4; j += stride) g_agg2[j] = z;
    for (int j = i; j < Nn;           j += stride) g_deg[j]  = 0;
    for (int j = i; j < Bb * HID;     j += stride) g_hg[j]   = 0.f;
    if (i < Bb) g_cnt[i] = 0.f;
}

__global__ void k_deg_cnt(const int* __restrict__ dst,
                          const int* __restrict__ graph_ids) {
    int i = blockIdx.x * blockDim.x + threadIdx.x;
    if (i < Ee) atomicAdd(&g_deg[dst[i]], 1);
    if (i < Nn) atomicAdd(&g_cnt[graph_ids[i]], 1.0f);
}

__global__ void k_dinv() {
    int i = blockIdx.x * blockDim.x + threadIdx.x;
    if (i >= Nn) return;
    int d = g_deg[i];
    g_dinv[i] = (d > 0) ? 1.0f / (float)d : 0.0f;
}

// h0[n] = emb[node_ids[n]]   (8 float4 per node)
__global__ void k_gather(const int* __restrict__ node_ids,
                         const float4* __restrict__ emb) {
    int t = blockIdx.x * blockDim.x + threadIdx.x;
    if (t >= Nn * 8) return;
    int n = t >> 3, c = t & 7;
    g_h0[n * 8 + c] = emb[node_ids[n] * 8 + c];
}

// agg1[dst] += h0[src]   (8 lanes per edge, coalesced float4)
__global__ void k_scatter1(const int* __restrict__ src,
                           const int* __restrict__ dst) {
    int t = blockIdx.x * blockDim.x + threadIdx.x;
    if (t >= Ee * 8) return;
    int e = t >> 3, c = t & 7;
    int s = __ldg(src + e), d = __ldg(dst + e);
    red4(&g_agg1[d * 8 + c], g_h0[s * 8 + c]);
}

// h1 = relu(h0 @ Ws1 + (agg1*dinv) @ Wn1 + b1)
__global__ void __launch_bounds__(256)
k_update1(const float* __restrict__ Wself, const float* __restrict__ Wneigh,
          const float* __restrict__ b) {
    __shared__ float sWs[EMB * HID];
    __shared__ float sWn[EMB * HID];
    __shared__ float sb[HID];
    int tid = threadIdx.x;
    for (int i = tid; i < EMB * HID; i += 256) { sWs[i] = Wself[i]; sWn[i] = Wneigh[i]; }
    if (tid < HID) sb[tid] = b[tid];
    __syncthreads();

    int n = blockIdx.x * 256 + tid;
    if (n >= Nn) return;

    float acc[HID];
    #pragma unroll
    for (int j = 0; j < HID; j++) acc[j] = sb[j];

    float dinv = g_dinv[n];
    #pragma unroll 1
    for (int k4 = 0; k4 < EMB / 4; k4++) {
        float4 h = g_h0[n * 8 + k4];
        float4 a = g_agg1[n * 8 + k4];
        a.x *= dinv; a.y *= dinv; a.z *= dinv; a.w *= dinv;
        const float4* ws = (const float4*)&sWs[(k4 * 4) * HID];
        const float4* wn = (const float4*)&sWn[(k4 * 4) * HID];
        #pragma unroll
        for (int j4 = 0; j4 < HID / 4; j4++) {
            float4 w0 = ws[j4];              float4 w1 = ws[16 + j4];
            float4 w2 = ws[32 + j4];         float4 w3 = ws[48 + j4];
            float4 v0 = wn[j4];              float4 v1 = wn[16 + j4];
            float4 v2 = wn[32 + j4];         float4 v3 = wn[48 + j4];
            acc[j4*4+0] += h.x*w0.x + h.y*w1.x + h.z*w2.x + h.w*w3.x
                         + a.x*v0.x + a.y*v1.x + a.z*v2.x + a.w*v3.x;
            acc[j4*4+1] += h.x*w0.y + h.y*w1.y + h.z*w2.y + h.w*w3.y
                         + a.x*v0.y + a.y*v1.y + a.z*v2.y + a.w*v3.y;
            acc[j4*4+2] += h.x*w0.z + h.y*w1.z + h.z*w2.z + h.w*w3.z
                         + a.x*v0.z + a.y*v1.z + a.z*v2.z + a.w*v3.z;
            acc[j4*4+3] += h.x*w0.w + h.y*w1.w + h.z*w2.w + h.w*w3.w
                         + a.x*v0.w + a.y*v1.w + a.z*v2.w + a.w*v3.w;
        }
    }
    #pragma unroll
    for (int j4 = 0; j4 < HID / 4; j4++) {
        float4 o;
        o.x = fmaxf(acc[j4*4+0], 0.f);
        o.y = fmaxf(acc[j4*4+1], 0.f);
        o.z = fmaxf(acc[j4*4+2], 0.f);
        o.w = fmaxf(acc[j4*4+3], 0.f);
        g_h1[n * 16 + j4] = o;
    }
}

// agg2[dst] += h1[src]   (16 lanes per edge)
__global__ void k_scatter2(const int* __restrict__ src,
                           const int* __restrict__ dst) {
    int t = blockIdx.x * blockDim.x + threadIdx.x;
    if (t >= Ee * 16) return;
    int e = t >> 4, c = t & 15;
    int s = __ldg(src + e), d = __ldg(dst + e);
    red4(&g_agg2[d * 16 + c], g_h1[s * 16 + c]);
}

// h2 = relu(h1 @ Ws2 + (agg2*dinv) @ Wn2 + b2); pool: hg[graph] += h2
__global__ void __launch_bounds__(256)
k_update2(const float* __restrict__ Wself, const float* __restrict__ Wneigh,
          const float* __restrict__ b, const int* __restrict__ graph_ids) {
    __shared__ float sWs[HID * HID];   // 16 KB
    __shared__ float sWn[HID * HID];   // 16 KB
    __shared__ float sb[HID];
    int tid = threadIdx.x;
    for (int i = tid; i < HID * HID; i += 256) { sWs[i] = Wself[i]; sWn[i] = Wneigh[i]; }
    if (tid < HID) sb[tid] = b[tid];
    __syncthreads();

    int n = blockIdx.x * 256 + tid;
    if (n >= Nn) return;

    float acc[HID];
    #pragma unroll
    for (int j = 0; j < HID; j++) acc[j] = sb[j];

    float dinv = g_dinv[n];
    #pragma unroll 1
    for (int k4 = 0; k4 < HID / 4; k4++) {
        float4 h = g_h1[n * 16 + k4];
        float4 a = g_agg2[n * 16 + k4];
        a.x *= dinv; a.y *= dinv; a.z *= dinv; a.w *= dinv;
        const float4* ws = (const float4*)&sWs[(k4 * 4) * HID];
        const float4* wn = (const float4*)&sWn[(k4 * 4) * HID];
        #pragma unroll
        for (int j4 = 0; j4 < HID / 4; j4++) {
            float4 w0 = ws[j4];              float4 w1 = ws[16 + j4];
            float4 w2 = ws[32 + j4];         float4 w3 = ws[48 + j4];
            float4 v0 = wn[j4];              float4 v1 = wn[16 + j4];
            float4 v2 = wn[32 + j4];         float4 v3 = wn[48 + j4];
            acc[j4*4+0] += h.x*w0.x + h.y*w1.x + h.z*w2.x + h.w*w3.x
                         + a.x*v0.x + a.y*v1.x + a.z*v2.x + a.w*v3.x;
            acc[j4*4+1] += h.x*w0.y + h.y*w1.y + h.z*w2.y + h.w*w3.y
                         + a.x*v0.y + a.y*v1.y + a.z*v2.y + a.w*v3.y;
            acc[j4*4+2] += h.x*w0.z + h.y*w1.z + h.z*w2.z + h.w*w3.z
                         + a.x*v0.z + a.y*v1.z + a.z*v2.z + a.w*v3.z;
            acc[j4*4+3] += h.x*w0.w + h.y*w1.w + h.z*w2.w + h.w*w3.w
                         + a.x*v0.w + a.y*v1.w + a.z*v2.w + a.w*v3.w;
        }
    }

    int g = graph_ids[n];
    float4* hgv = (float4*)&g_hg[g * HID];
    #pragma unroll
    for (int j4 = 0; j4 < HID / 4; j4++) {
        float4 o;
        o.x = fmaxf(acc[j4*4+0], 0.f);
        o.y = fmaxf(acc[j4*4+1], 0.f);
        o.z = fmaxf(acc[j4*4+2], 0.f);
        o.w = fmaxf(acc[j4*4+3], 0.f);
        red4(&hgv[j4], o);
    }
}

// scorer: out[g] = relu(hg_mean @ Ws1 + bs1) @ Ws2 + bs2
__global__ void k_final(const float* __restrict__ Ws1, const float* __restrict__ bs1,
                        const float* __restrict__ Ws2, const float* __restrict__ bs2,
                        float* __restrict__ out) {
    __shared__ float sW[HID * HID];
    int tid = threadIdx.x;
    for (int i = tid; i < HID * HID; i += 64) sW[i] = Ws1[i];
    __syncthreads();

    int g = blockIdx.x * 64 + tid;
    if (g >= Bb) return;

    float inv = 1.0f / fmaxf(g_cnt[g], 1.0f);
    float hv[HID];
    #pragma unroll
    for (int k = 0; k < HID; k++) hv[k] = g_hg[g * HID + k] * inv;

    float s = bs2[0];
    #pragma unroll 1
    for (int j = 0; j < HID; j++) {
        float t = bs1[j];
        #pragma unroll
        for (int k = 0; k < HID; k++) t += hv[k] * sW[k * HID + j];
        s += fmaxf(t, 0.f) * Ws2[j];
    }
    out[g] = s;
}

// ---------------- launcher ----------------
extern "C" void kernel_launch(void* const* d_in, const int* in_sizes, int n_in,
                              void* d_out, int out_size) {
    const int*    node_ids  = (const int*)   d_in[0];
    const int*    src       = (const int*)   d_in[1];
    const int*    dst       = (const int*)   d_in[2];
    const int*    graph_ids = (const int*)   d_in[3];
    const float4* emb       = (const float4*)d_in[4];
    const float*  W_self1   = (const float*) d_in[5];
    const float*  W_neigh1  = (const float*) d_in[6];
    const float*  b1        = (const float*) d_in[7];
    const float*  W_self2   = (const float*) d_in[8];
    const float*  W_neigh2  = (const float*) d_in[9];
    const float*  b2        = (const float*) d_in[10];
    const float*  Ws1       = (const float*) d_in[11];
    const float*  bs1       = (const float*) d_in[12];
    const float*  Ws2       = (const float*) d_in[13];
    const float*  bs2       = (const float*) d_in[14];
    float* out = (float*)d_out;

    k_zero    <<<4096, 256>>>();
    k_deg_cnt <<<(Ee + 255) / 256, 256>>>(dst, graph_ids);
    k_dinv    <<<(Nn + 255) / 256, 256>>>();
    k_gather  <<<(Nn * 8 + 255) / 256, 256>>>(node_ids, emb);
    k_scatter1<<<(Ee * 8 + 255) / 256, 256>>>(src, dst);
    k_update1 <<<(Nn + 255) / 256, 256>>>(W_self1, W_neigh1, b1);
    k_scatter2<<<(Ee * 16 + 255) / 256, 256>>>(src, dst);
    k_update2 <<<(Nn + 255) / 256, 256>>>(W_self2, W_neigh2, b2, graph_ids);
    k_final   <<<(Bb + 63) / 64, 64>>>(Ws1, bs1, Ws2, bs2, out);
}

// round 2
// speedup vs baseline: 1.3160x; 1.3160x over previous
#include <cuda_runtime.h>

#define Nn   200000
#define Ee   3200000
#define Bb   512
#define EMB  32
#define HID  64
#define NB   196        // ceil(Nn/1024) scan blocks

// ---------------- scratch (device globals; no allocation allowed) ----------------
__device__ float4 g_h0  [Nn * EMB / 4];   // 25.6 MB
__device__ float4 g_agg1[Nn * EMB / 4];   // 25.6 MB
__device__ float4 g_h1  [Nn * HID / 4];   // 51.2 MB
__device__ float4 g_agg2[Nn * HID / 4];   // 51.2 MB
__device__ int    g_csr [Ee];             // 12.8 MB neighbor (src) lists grouped by dst
__device__ int    g_rowptr[Nn];
__device__ int    g_cursor[Nn];
__device__ int    g_blk [NB];
__device__ int    g_blkoff[NB];
__device__ float  g_hg  [Bb * HID];
__device__ float  g_cnt [Bb];
__device__ int    g_deg [Nn];
__device__ float  g_dinv[Nn];

// vectorized no-return global reduction (sm_90+)
__device__ __forceinline__ void red4(float4* p, float4 v) {
    asm volatile("red.global.add.v4.f32 [%0], {%1,%2,%3,%4};"
                 :: "l"(p), "f"(v.x), "f"(v.y), "f"(v.z), "f"(v.w) : "memory");
}

// ---------------- setup kernels ----------------

__global__ void k_zero() {
    int i = blockIdx.x * blockDim.x + threadIdx.x;
    int stride = gridDim.x * blockDim.x;
    for (int j = i; j < Nn;       j += stride) g_deg[j] = 0;
    for (int j = i; j < Bb * HID; j += stride) g_hg[j]  = 0.f;
    if (i < Bb) g_cnt[i] = 0.f;
}

__global__ void k_deg_cnt(const int* __restrict__ dst,
                          const int* __restrict__ graph_ids) {
    int i = blockIdx.x * blockDim.x + threadIdx.x;
    if (i < Ee) atomicAdd(&g_deg[dst[i]], 1);
    if (i < Nn) atomicAdd(&g_cnt[graph_ids[i]], 1.0f);
}

// block-level inclusive scan of deg (1024/block) -> local exclusive + block sums
__global__ void k_scan1() {
    __shared__ int sh[1024];
    int t = threadIdx.x;
    int i = blockIdx.x * 1024 + t;
    int v = (i < Nn) ? g_deg[i] : 0;
    sh[t] = v; __syncthreads();
    #pragma unroll
    for (int off = 1; off < 1024; off <<= 1) {
        int x = (t >= off) ? sh[t - off] : 0;
        __syncthreads();
        sh[t] += x;
        __syncthreads();
    }
    if (i < Nn) g_rowptr[i] = sh[t] - v;      // local exclusive
    if (t == 1023) g_blk[blockIdx.x] = sh[1023];
}

__global__ void k_scan2() {   // single block of 256 scans NB block sums
    __shared__ int sh[256];
    int t = threadIdx.x;
    int v = (t < NB) ? g_blk[t] : 0;
    sh[t] = v; __syncthreads();
    #pragma unroll
    for (int off = 1; off < 256; off <<= 1) {
        int x = (t >= off) ? sh[t - off] : 0;
        __syncthreads();
        sh[t] += x;
        __syncthreads();
    }
    if (t < NB) g_blkoff[t] = sh[t] - v;      // exclusive block offsets
}

__global__ void k_scan3() {   // add offsets; init cursor; compute dinv
    int i = blockIdx.x * blockDim.x + threadIdx.x;
    if (i >= Nn) return;
    int r = g_rowptr[i] + g_blkoff[i >> 10];
    g_rowptr[i] = r;
    g_cursor[i] = r;
    int d = g_deg[i];
    g_dinv[i] = (d > 0) ? 1.0f / (float)d : 0.0f;
}

__global__ void k_fill(const int* __restrict__ src, const int* __restrict__ dst) {
    int e = blockIdx.x * blockDim.x + threadIdx.x;
    if (e >= Ee) return;
    int p = atomicAdd(&g_cursor[dst[e]], 1);
    g_csr[p] = src[e];
}

// h0[n] = emb[node_ids[n]]
__global__ void k_gather(const int* __restrict__ node_ids,
                         const float4* __restrict__ emb) {
    int t = blockIdx.x * blockDim.x + threadIdx.x;
    if (t >= Nn * 8) return;
    int n = t >> 3, c = t & 7;
    g_h0[n * 8 + c] = emb[node_ids[n] * 8 + c];
}

// ---------------- node-parallel mean aggregation (no atomics) ----------------

// agg1[n] = dinv[n] * sum_{s in N(n)} h0[s]   -- 8 threads/node, float4 each
__global__ void k_agg1() {
    int t = blockIdx.x * blockDim.x + threadIdx.x;
    if (t >= Nn * 8) return;
    int n = t >> 3, c = t & 7;
    int beg = g_rowptr[n], cnt = g_deg[n];
    float4 acc = make_float4(0.f, 0.f, 0.f, 0.f);
    int i = 0;
    for (; i + 3 < cnt; i += 4) {
        int s0 = __ldg(&g_csr[beg + i + 0]);
        int s1 = __ldg(&g_csr[beg + i + 1]);
        int s2 = __ldg(&g_csr[beg + i + 2]);
        int s3 = __ldg(&g_csr[beg + i + 3]);
        float4 v0 = g_h0[s0 * 8 + c];
        float4 v1 = g_h0[s1 * 8 + c];
        float4 v2 = g_h0[s2 * 8 + c];
        float4 v3 = g_h0[s3 * 8 + c];
        acc.x += (v0.x + v1.x) + (v2.x + v3.x);
        acc.y += (v0.y + v1.y) + (v2.y + v3.y);
        acc.z += (v0.z + v1.z) + (v2.z + v3.z);
        acc.w += (v0.w + v1.w) + (v2.w + v3.w);
    }
    for (; i < cnt; i++) {
        int s = __ldg(&g_csr[beg + i]);
        float4 v = g_h0[s * 8 + c];
        acc.x += v.x; acc.y += v.y; acc.z += v.z; acc.w += v.w;
    }
    float dinv = g_dinv[n];
    acc.x *= dinv; acc.y *= dinv; acc.z *= dinv; acc.w *= dinv;
    g_agg1[n * 8 + c] = acc;
}

// agg2[n] = dinv[n] * sum h1[s]   -- 16 threads/node
__global__ void k_agg2() {
    int t = blockIdx.x * blockDim.x + threadIdx.x;
    if (t >= Nn * 16) return;
    int n = t >> 4, c = t & 15;
    int beg = g_rowptr[n], cnt = g_deg[n];
    float4 acc = make_float4(0.f, 0.f, 0.f, 0.f);
    int i = 0;
    for (; i + 3 < cnt; i += 4) {
        int s0 = __ldg(&g_csr[beg + i + 0]);
        int s1 = __ldg(&g_csr[beg + i + 1]);
        int s2 = __ldg(&g_csr[beg + i + 2]);
        int s3 = __ldg(&g_csr[beg + i + 3]);
        float4 v0 = g_h1[s0 * 16 + c];
        float4 v1 = g_h1[s1 * 16 + c];
        float4 v2 = g_h1[s2 * 16 + c];
        float4 v3 = g_h1[s3 * 16 + c];
        acc.x += (v0.x + v1.x) + (v2.x + v3.x);
        acc.y += (v0.y + v1.y) + (v2.y + v3.y);
        acc.z += (v0.z + v1.z) + (v2.z + v3.z);
        acc.w += (v0.w + v1.w) + (v2.w + v3.w);
    }
    for (; i < cnt; i++) {
        int s = __ldg(&g_csr[beg + i]);
        float4 v = g_h1[s * 16 + c];
        acc.x += v.x; acc.y += v.y; acc.z += v.z; acc.w += v.w;
    }
    float dinv = g_dinv[n];
    acc.x *= dinv; acc.y *= dinv; acc.z *= dinv; acc.w *= dinv;
    g_agg2[n * 16 + c] = acc;
}

// ---------------- dense updates ----------------

// h1 = relu(h0 @ Ws1 + agg1 @ Wn1 + b1)   (agg1 pre-scaled by dinv)
__global__ void __launch_bounds__(256)
k_update1(const float* __restrict__ Wself, const float* __restrict__ Wneigh,
          const float* __restrict__ b) {
    __shared__ float sWs[EMB * HID];
    __shared__ float sWn[EMB * HID];
    __shared__ float sb[HID];
    int tid = threadIdx.x;
    for (int i = tid; i < EMB * HID; i += 256) { sWs[i] = Wself[i]; sWn[i] = Wneigh[i]; }
    if (tid < HID) sb[tid] = b[tid];
    __syncthreads();

    int n = blockIdx.x * 256 + tid;
    if (n >= Nn) return;

    float acc[HID];
    #pragma unroll
    for (int j = 0; j < HID; j++) acc[j] = sb[j];

    #pragma unroll 1
    for (int k4 = 0; k4 < EMB / 4; k4++) {
        float4 h = g_h0[n * 8 + k4];
        float4 a = g_agg1[n * 8 + k4];
        const float4* ws = (const float4*)&sWs[(k4 * 4) * HID];
        const float4* wn = (const float4*)&sWn[(k4 * 4) * HID];
        #pragma unroll
        for (int j4 = 0; j4 < HID / 4; j4++) {
            float4 w0 = ws[j4];      float4 w1 = ws[16 + j4];
            float4 w2 = ws[32 + j4]; float4 w3 = ws[48 + j4];
            float4 v0 = wn[j4];      float4 v1 = wn[16 + j4];
            float4 v2 = wn[32 + j4]; float4 v3 = wn[48 + j4];
            acc[j4*4+0] += h.x*w0.x + h.y*w1.x + h.z*w2.x + h.w*w3.x
                         + a.x*v0.x + a.y*v1.x + a.z*v2.x + a.w*v3.x;
            acc[j4*4+1] += h.x*w0.y + h.y*w1.y + h.z*w2.y + h.w*w3.y
                         + a.x*v0.y + a.y*v1.y + a.z*v2.y + a.w*v3.y;
            acc[j4*4+2] += h.x*w0.z + h.y*w1.z + h.z*w2.z + h.w*w3.z
                         + a.x*v0.z + a.y*v1.z + a.z*v2.z + a.w*v3.z;
            acc[j4*4+3] += h.x*w0.w + h.y*w1.w + h.z*w2.w + h.w*w3.w
                         + a.x*v0.w + a.y*v1.w + a.z*v2.w + a.w*v3.w;
        }
    }
    #pragma unroll
    for (int j4 = 0; j4 < HID / 4; j4++) {
        float4 o;
        o.x = fmaxf(acc[j4*4+0], 0.f);
        o.y = fmaxf(acc[j4*4+1], 0.f);
        o.z = fmaxf(acc[j4*4+2], 0.f);
        o.w = fmaxf(acc[j4*4+3], 0.f);
        g_h1[n * 16 + j4] = o;
    }
}

// h2 = relu(h1 @ Ws2 + agg2 @ Wn2 + b2); pooled: hg[graph] += h2
__global__ void __launch_bounds__(256)
k_update2(const float* __restrict__ Wself, const float* __restrict__ Wneigh,
          const float* __restrict__ b, const int* __restrict__ graph_ids) {
    __shared__ float sWs[HID * HID];
    __shared__ float sWn[HID * HID];
    __shared__ float sb[HID];
    int tid = threadIdx.x;
    for (int i = tid; i < HID * HID; i += 256) { sWs[i] = Wself[i]; sWn[i] = Wneigh[i]; }
    if (tid < HID) sb[tid] = b[tid];
    __syncthreads();

    int n = blockIdx.x * 256 + tid;
    if (n >= Nn) return;

    float acc[HID];
    #pragma unroll
    for (int j = 0; j < HID; j++) acc[j] = sb[j];

    #pragma unroll 1
    for (int k4 = 0; k4 < HID / 4; k4++) {
        float4 h = g_h1[n * 16 + k4];
        float4 a = g_agg2[n * 16 + k4];
        const float4* ws = (const float4*)&sWs[(k4 * 4) * HID];
        const float4* wn = (const float4*)&sWn[(k4 * 4) * HID];
        #pragma unroll
        for (int j4 = 0; j4 < HID / 4; j4++) {
            float4 w0 = ws[j4];      float4 w1 = ws[16 + j4];
            float4 w2 = ws[32 + j4]; float4 w3 = ws[48 + j4];
            float4 v0 = wn[j4];      float4 v1 = wn[16 + j4];
            float4 v2 = wn[32 + j4]; float4 v3 = wn[48 + j4];
            acc[j4*4+0] += h.x*w0.x + h.y*w1.x + h.z*w2.x + h.w*w3.x
                         + a.x*v0.x + a.y*v1.x + a.z*v2.x + a.w*v3.x;
            acc[j4*4+1] += h.x*w0.y + h.y*w1.y + h.z*w2.y + h.w*w3.y
                         + a.x*v0.y + a.y*v1.y + a.z*v2.y + a.w*v3.y;
            acc[j4*4+2] += h.x*w0.z + h.y*w1.z + h.z*w2.z + h.w*w3.z
                         + a.x*v0.z + a.y*v1.z + a.z*v2.z + a.w*v3.z;
            acc[j4*4+3] += h.x*w0.w + h.y*w1.w + h.z*w2.w + h.w*w3.w
                         + a.x*v0.w + a.y*v1.w + a.z*v2.w + a.w*v3.w;
        }
    }

    int g = graph_ids[n];
    float4* hgv = (float4*)&g_hg[g * HID];
    #pragma unroll
    for (int j4 = 0; j4 < HID / 4; j4++) {
        float4 o;
        o.x = fmaxf(acc[j4*4+0], 0.f);
        o.y = fmaxf(acc[j4*4+1], 0.f);
        o.z = fmaxf(acc[j4*4+2], 0.f);
        o.w = fmaxf(acc[j4*4+3], 0.f);
        red4(&hgv[j4], o);
    }
}

// scorer: out[g] = relu(hg_mean @ Ws1 + bs1) @ Ws2 + bs2
__global__ void k_final(const float* __restrict__ Ws1, const float* __restrict__ bs1,
                        const float* __restrict__ Ws2, const float* __restrict__ bs2,
                        float* __restrict__ out) {
    __shared__ float sW[HID * HID];
    int tid = threadIdx.x;
    for (int i = tid; i < HID * HID; i += 64) sW[i] = Ws1[i];
    __syncthreads();

    int g = blockIdx.x * 64 + tid;
    if (g >= Bb) return;

    float inv = 1.0f / fmaxf(g_cnt[g], 1.0f);
    float hv[HID];
    #pragma unroll
    for (int k = 0; k < HID; k++) hv[k] = g_hg[g * HID + k] * inv;

    float s = bs2[0];
    #pragma unroll 1
    for (int j = 0; j < HID; j++) {
        float t = bs1[j];
        #pragma unroll
        for (int k = 0; k < HID; k++) t += hv[k] * sW[k * HID + j];
        s += fmaxf(t, 0.f) * Ws2[j];
    }
    out[g] = s;
}

// ---------------- launcher ----------------
extern "C" void kernel_launch(void* const* d_in, const int* in_sizes, int n_in,
                              void* d_out, int out_size) {
    const int*    node_ids  = (const int*)   d_in[0];
    const int*    src       = (const int*)   d_in[1];
    const int*    dst       = (const int*)   d_in[2];
    const int*    graph_ids = (const int*)   d_in[3];
    const float4* emb       = (const float4*)d_in[4];
    const float*  W_self1   = (const float*) d_in[5];
    const float*  W_neigh1  = (const float*) d_in[6];
    const float*  b1        = (const float*) d_in[7];
    const float*  W_self2   = (const float*) d_in[8];
    const float*  W_neigh2  = (const float*) d_in[9];
    const float*  b2        = (const float*) d_in[10];
    const float*  Ws1       = (const float*) d_in[11];
    const float*  bs1       = (const float*) d_in[12];
    const float*  Ws2       = (const float*) d_in[13];
    const float*  bs2       = (const float*) d_in[14];
    float* out = (float*)d_out;

    k_zero   <<<2048, 256>>>();
    k_deg_cnt<<<(Ee + 255) / 256, 256>>>(dst, graph_ids);
    k_scan1  <<<NB, 1024>>>();
    k_scan2  <<<1, 256>>>();
    k_scan3  <<<(Nn + 255) / 256, 256>>>();
    k_fill   <<<(Ee + 255) / 256, 256>>>(src, dst);
    k_gather <<<(Nn * 8 + 255) / 256, 256>>>(node_ids, emb);
    k_agg1   <<<(Nn * 8 + 255) / 256, 256>>>();
    k_update1<<<(Nn + 255) / 256, 256>>>(W_self1, W_neigh1, b1);
    k_agg2   <<<(Nn * 16 + 255) / 256, 256>>>();
    k_update2<<<(Nn + 255) / 256, 256>>>(W_self2, W_neigh2, b2, graph_ids);
    k_final  <<<(Bb + 63) / 64, 64>>>(Ws1, bs1, Ws2, bs2, out);
}